// round 8
// baseline (speedup 1.0000x reference)
#include <cuda_runtime.h>
#include <cuda_fp16.h>

// Radon forward projection, sm_103a — round 8.
// R7 left crossbar conflicts (~1.64x) as the binding constraint (L1 60%, issue
// 54% capped via MIO backpressure). This round adds a row swizzle with zero
// XORs: row stride 144 (multiple of 16 double-banks) + per-row additive offset
// ((row&3)<<2) entries, folded into the address IMAD. Spreads resonant lane
// strides across 4 double-bank groups; column +1 taps keep immediate offsets.

#define STRIDE_E 144                          // entries per row (mult of 16)
#define ROWS_E   131
#define SMEM_ELEMS (ROWS_E * STRIDE_E)        // 18864 entries (8 B each)
#define SMEM_BYTES (SMEM_ELEMS * 8 + 64)      // 150976 B + trig table

#define N_ANG 285
#define N_DET 183
#define SINO  (N_ANG * N_DET)                 // 52155
#define NTHR  768

typedef unsigned long long u64;

__device__ __forceinline__ u64 pk2(float x, float y) {
    u64 u; asm("mov.b64 %0, {%1, %2};" : "=l"(u) : "f"(x), "f"(y)); return u;
}
__device__ __forceinline__ void upk2(u64 u, float& x, float& y) {
    asm("mov.b64 {%0, %1}, %2;" : "=f"(x), "=f"(y) : "l"(u));
}
__device__ __forceinline__ u64 fma2_(u64 a, u64 b, u64 c) {
    u64 d; asm("fma.rn.f32x2 %0, %1, %2, %3;" : "=l"(d) : "l"(a), "l"(b), "l"(c)); return d;
}
__device__ __forceinline__ u64 add2_(u64 a, u64 b) {
    u64 d; asm("add.rn.f32x2 %0, %1, %2;" : "=l"(d) : "l"(a), "l"(b)); return d;
}
__device__ __forceinline__ __half2 as_h2(unsigned u) {
    __half2 h; asm("mov.b32 %0, %1;" : "=r"(reinterpret_cast<unsigned&>(h)) : "r"(u)); return h;
}

__global__ __launch_bounds__(NTHR, 1)
void radon_fp_kernel(const float* __restrict__ x, float* __restrict__ out)
{
    extern __shared__ u64 imgs[];
    float2* trig = (float2*)(imgs + SMEM_ELEMS);

    const int tid = threadIdx.x;
    const int bg  = blockIdx.y;          // batch group: batches 4bg .. 4bg+3
    const int sub = tid / 192;           // which of 4 concurrent angles (0..3)
    const int det = tid % 192;

    const float* gx0 = x + (4 * bg)     * 16384;
    const float* gx1 = x + (4 * bg + 1) * 16384;
    const float* gx2 = x + (4 * bg + 2) * 16384;
    const float* gx3 = x + (4 * bg + 3) * 16384;

    // Fill padded 4-batch fp16 image. Array coords (ar, ac) = pixel (ar-1, ac-1),
    // ar, ac in [0, 130]; stored at ar*144 + ((ar&3)<<2) + ac. Gap entries in
    // each row are never read.
    for (int e = tid; e < ROWS_E * 131; e += NTHR) {
        int ar = e / 131;
        int ac = e - ar * 131;
        int pr = ar - 1, pc = ac - 1;
        bool in = ((unsigned)pr < 128u) & ((unsigned)pc < 128u);
        int gi = pr * 128 + pc;
        float v0 = in ? gx0[gi] : 0.0f;
        float v1 = in ? gx1[gi] : 0.0f;
        float v2 = in ? gx2[gi] : 0.0f;
        float v3 = in ? gx3[gi] : 0.0f;
        __half2 L = __floats2half2_rn(v0, v1);
        __half2 H = __floats2half2_rn(v2, v3);
        unsigned lo = reinterpret_cast<unsigned&>(L);
        unsigned hi = reinterpret_cast<unsigned&>(H);
        imgs[ar * STRIDE_E + ((ar & 3) << 2) + ac] = ((u64)hi << 32) | (u64)lo;
    }
    // Double-precision trig for this block's 4 angles.
    if (tid < 4) {
        int a = 4 * blockIdx.x + tid;
        if (a < N_ANG) {
            double sd, cd;
            sincospi((a + 0.5) / 285.0, &sd, &cd);
            trig[tid] = make_float2((float)sd, (float)cd);
        }
    }
    __syncthreads();

    // Constants (double-derived)
    const float RHOf = 28.284271247461902f;
    const float KD   = 0.47140452079103173f;        // DT/DX, DX = 0.3125
    const float t0c  = -28.284271247461902f + 0.5f * 0.14731391274719688f;
    const float scale = 0.012276159395599740f;      // DT/12
    const float s = fmaf((float)det + 0.5f, 2.0f * RHOf / 183.0f, -RHOf);

    const u64 BIG2   = pk2( 8388608.f,  8388608.f);
    const u64 nBIG2  = pk2(-8388608.f, -8388608.f);
    const u64 half2c = pk2(0.5f, 0.5f);
    const u64 neg1   = pk2(-1.f, -1.f);
    const u64 one2   = pk2(1.f, 1.f);
    const uint2* img2 = (const uint2*)imgs;

    const int a = 4 * blockIdx.x + sub;
    if (det < N_DET && a < N_ANG) {
        float2 sc = trig[sub];
        float sn = sc.x, cs = sc.y;
        float d0 = KD * cs;
        float d1 = KD * sn;
        // i0 = (-s*sn + t*cs + 20)*3.2 - 0.5, t = t0c + k*DT
        float c0 = fmaf(-s, sn, fmaf(t0c, cs, 20.0f)) * 3.2f - 0.5f;
        float c1 = fmaf( s, cs, fmaf(t0c, sn, 20.0f)) * 3.2f - 0.5f;

        // Valid window (content zero outside i in (-1, 128); safe to 129.49)
        const float LO = -0.999f, HI = 128.01f;
        float ra = (LO - c0) / d0, rb = (HI - c0) / d0;
        float klo = fmaxf(0.0f,  fminf(ra, rb));
        float khi = fminf(383.0f, fmaxf(ra, rb));
        ra = (LO - c1) / d1; rb = (HI - c1) / d1;
        klo = fmaxf(klo, fminf(ra, rb));
        khi = fminf(khi, fmaxf(ra, rb));
        int k0 = (int)ceilf(klo);
        int k1 = (int)floorf(khi);

        u64 d01  = pk2(d0, d1);
        u64 c01m = pk2(c0 + 1.5f, c1 + 1.5f);   // t = i + 1.5
        u64 kf2  = pk2((float)k0, (float)k0);
        u64 accA = 0ull;                        // batches 0,1 (fp32 pair)
        u64 accB = 0ull;                        // batches 2,3

        #pragma unroll 4
        for (int k = k0; k <= k1; ++k) {
            u64 t01  = fma2_(kf2, d01, c01m);        // i+1.5, both axes
            u64 y01  = add2_(t01, BIG2);             // round-to-int in mantissa
            u64 fl01 = add2_(y01, nBIG2);            // round(t) = floor(i)+2
            u64 fr01 = add2_(fma2_(fl01, neg1, t01), half2c); // frac in [0,1]
            kf2 = add2_(kf2, one2);
            int n0 = (int)((unsigned)y01 & 255u);          // floor(i0)+2 in [1,130]
            int n1 = (int)((unsigned)(y01 >> 32) & 255u);  // floor(i1)+2
            // Rows accessed: R = n0-1, R+1 = n0; cols: C = n1-1, C+1.
            // addr(r, c) = r*144 + ((r&3)<<2) + c
            int m0 = ((n0 - 1) & 3) << 2;
            int m1 = ( n0      & 3) << 2;
            int base = n0 * STRIDE_E + n1;
            const uint2* pr0 = img2 + (base + m0 - (STRIDE_E + 1)); // row R,   col C
            const uint2* pr1 = img2 + (base + m1 - 1);              // row R+1, col C
            uint2 q00 = pr0[0];
            uint2 q01 = pr0[1];
            uint2 q10 = pr1[0];
            uint2 q11 = pr1[1];
            float f0, f1; upk2(fr01, f0, f1);
            __half2 f0h = __float2half2_rn(f0);
            __half2 f1h = __float2half2_rn(f1);
            // batches 0,1 (low words)
            {
                __half2 a00 = as_h2(q00.x), a01 = as_h2(q01.x);
                __half2 a10 = as_h2(q10.x), a11 = as_h2(q11.x);
                __half2 m0h = __hfma2(f1h, __hsub2(a01, a00), a00);
                __half2 m1h = __hfma2(f1h, __hsub2(a11, a10), a10);
                __half2 r   = __hfma2(f0h, __hsub2(m1h, m0h), m0h);
                accA = add2_(accA, pk2(__low2float(r), __high2float(r)));
            }
            // batches 2,3 (high words)
            {
                __half2 b00 = as_h2(q00.y), b01 = as_h2(q01.y);
                __half2 b10 = as_h2(q10.y), b11 = as_h2(q11.y);
                __half2 m0h = __hfma2(f1h, __hsub2(b01, b00), b00);
                __half2 m1h = __hfma2(f1h, __hsub2(b11, b10), b10);
                __half2 r   = __hfma2(f0h, __hsub2(m1h, m0h), m0h);
                accB = add2_(accB, pk2(__low2float(r), __high2float(r)));
            }
        }

        int ob = ((4 * bg) * N_ANG + a) * N_DET + det;
        float o0, o1, o2, o3;
        upk2(accA, o0, o1);
        upk2(accB, o2, o3);
        out[ob]            = o0 * scale;
        out[ob + SINO]     = o1 * scale;
        out[ob + 2 * SINO] = o2 * scale;
        out[ob + 3 * SINO] = o3 * scale;
    }
}

extern "C" void kernel_launch(void* const* d_in, const int* in_sizes, int n_in,
                              void* d_out, int out_size)
{
    const float* x = (const float*)d_in[0];
    float* out = (float*)d_out;

    static bool attr_set = false;
    if (!attr_set) {
        cudaFuncSetAttribute(radon_fp_kernel,
                             cudaFuncAttributeMaxDynamicSharedMemorySize, SMEM_BYTES);
        attr_set = true;
    }

    dim3 grid(72, 2);    // 72 angle-quads x 2 batch-groups = 144 blocks (1 wave)
    radon_fp_kernel<<<grid, NTHR, SMEM_BYTES>>>(x, out);
}